// round 17
// baseline (speedup 1.0000x reference)
#include <cuda_runtime.h>
#include <cuda_bf16.h>
#include <cstdint>

#define NN      8192
#define NODE    256
#define DEG     16
#define NFEAT   128
#define NHID    256
#define NCLASS  64

// ---------------- device scratch (no allocation allowed) --------------------
__device__ float    g_X  [NN * NFEAT];    // adj @ x
__device__ float    g_H  [NN * NHID];     // relu(gX @ W1)
__device__ float    g_T  [NN * NCLASS];   // gH @ W2
__device__ unsigned g_keep[NN];           // dedup bitmask per node
__device__ float    g_W1t[NHID * NFEAT];  // W1^T
__device__ float    g_W2t[NCLASS * NHID]; // W2^T

// pack two f32 -> bf16x2 (hi arg = upper half)
__device__ __forceinline__ uint32_t bf2(float hi, float lo) {
    uint32_t r; asm("cvt.rn.bf16x2.f32 %0, %1, %2;" : "=r"(r) : "f"(hi), "f"(lo));
    return r;
}
__device__ __forceinline__ void mma_bf16(float c[4], const uint32_t a[4], const uint32_t b[2]) {
    asm volatile(
        "mma.sync.aligned.m16n8k16.row.col.f32.bf16.bf16.f32 "
        "{%0,%1,%2,%3}, {%4,%5,%6,%7}, {%8,%9}, {%0,%1,%2,%3};"
        : "+f"(c[0]), "+f"(c[1]), "+f"(c[2]), "+f"(c[3])
        : "r"(a[0]), "r"(a[1]), "r"(a[2]), "r"(a[3]), "r"(b[0]), "r"(b[1]));
}
__device__ __forceinline__ void ldsm_x4(uint32_t r[4], uint32_t addr) {
    asm volatile("ldmatrix.sync.aligned.m8n8.x4.shared.b16 {%0,%1,%2,%3}, [%4];"
        : "=r"(r[0]), "=r"(r[1]), "=r"(r[2]), "=r"(r[3]) : "r"(addr));
}
__device__ __forceinline__ void ldsm_x2(uint32_t r[2], uint32_t addr) {
    asm volatile("ldmatrix.sync.aligned.m8n8.x2.shared.b16 {%0,%1}, [%2];"
        : "=r"(r[0]), "=r"(r[1]) : "r"(addr));
}

// Dynamic smem sizes for agg1
#define A1_SMX_FLT   (NODE * 32)
#define A1_EDGE_INT  (NODE * DEG)
#define A1_SMEM_B    ((A1_SMX_FLT + A1_EDGE_INT + NODE + NODE) * 4)

// ---------------------------------------------------------------------------
// K1: blocks 0..127 : agg1 — smem-staged adj @ x. CTA = (block, 32-col slice).
//     Also writes dedup masks (g==0 CTAs). blocks 128..175: W transposes.
// ---------------------------------------------------------------------------
__global__ __launch_bounds__(256)
void agg1_kernel(const float* __restrict__ x, const int* __restrict__ edge,
                 const float* __restrict__ W1, const float* __restrict__ W2,
                 float* __restrict__ gX, unsigned* __restrict__ keep_out,
                 float* __restrict__ W1t, float* __restrict__ W2t)
{
    extern __shared__ float dyn[];
    const int bid = blockIdx.x;
    const int tid = threadIdx.x;

    if (bid < 128) {
        float*    smx   = dyn;                                           // [256][32]
        int*      sedge = reinterpret_cast<int*>(dyn + A1_SMX_FLT);      // [256][16]
        unsigned* smask = reinterpret_cast<unsigned*>(sedge + A1_EDGE_INT);

        const int blk  = bid >> 2;
        const int g    = bid & 3;
        const int base = blk * NODE;

#pragma unroll
        for (int i = tid; i < NODE * 8; i += 256) {
            int r = i >> 3, qd = i & 7;
            *reinterpret_cast<float4*>(&smx[r * 32 + qd * 4]) =
                *reinterpret_cast<const float4*>(
                    x + (size_t)(base + r) * NFEAT + g * 32 + qd * 4);
        }
        {
            const int4* ep = reinterpret_cast<const int4*>(edge + (size_t)(base + tid) * DEG);
            int4 v0 = ep[0], v1 = ep[1], v2 = ep[2], v3 = ep[3];
            int e[16] = {v0.x, v0.y, v0.z, v0.w, v1.x, v1.y, v1.z, v1.w,
                         v2.x, v2.y, v2.z, v2.w, v3.x, v3.y, v3.z, v3.w};
            unsigned mask = 0;
#pragma unroll
            for (int i = 0; i < 16; ++i) {
                bool keep = e[i] >= 0;
#pragma unroll
                for (int p = 0; p < i; ++p) keep = keep && (e[i] != e[p]);
                if (keep) mask |= 1u << i;
                sedge[tid * DEG + i] = (e[i] >= 0) ? e[i] : 0;
            }
            smask[tid] = mask;
            if (g == 0) keep_out[base + tid] = mask;
        }
        __syncthreads();

        // explicit two-wave preload: 8 LDS.128 batched, then fma, twice
#pragma unroll
        for (int p = 0; p < 8; ++p) {
            const int nl = p * 32 + (tid >> 3);
            const int qd = tid & 7;
            const unsigned mask = smask[nl];
            int jr[16];
#pragma unroll
            for (int t = 0; t < DEG; ++t) jr[t] = sedge[nl * DEG + t];

            float4 a = make_float4(0.f, 0.f, 0.f, 0.f);
#pragma unroll
            for (int h = 0; h < 2; ++h) {
                float4 v[8];
#pragma unroll
                for (int t = 0; t < 8; ++t)
                    v[t] = *reinterpret_cast<const float4*>(
                        &smx[jr[h * 8 + t] * 32 + qd * 4]);
#pragma unroll
                for (int t = 0; t < 8; ++t) {
                    float fm = (float)((mask >> (h * 8 + t)) & 1u);
                    a.x = fmaf(v[t].x, fm, a.x);
                    a.y = fmaf(v[t].y, fm, a.y);
                    a.z = fmaf(v[t].z, fm, a.z);
                    a.w = fmaf(v[t].w, fm, a.w);
                }
            }
            *reinterpret_cast<float4*>(
                gX + (size_t)(base + nl) * NFEAT + g * 32 + qd * 4) = a;
        }
    } else {
        float* t = dyn;                         // [32][33]
        const float* src; float* dst; int R, C, tr, tc;
        if (bid < 160) { int b = bid - 128; src = W1; dst = W1t; R = NFEAT; C = NHID;  tr = b >> 3; tc = b & 7; }
        else           { int b = bid - 160; src = W2; dst = W2t; R = NHID;  C = NCLASS; tr = b >> 1; tc = b & 1; }
        const int r  = tid >> 3;
        const int fq = tid & 7;
        float4 v = *reinterpret_cast<const float4*>(src + (size_t)(tr * 32 + r) * C + tc * 32 + fq * 4);
        t[r * 33 + fq * 4 + 0] = v.x; t[r * 33 + fq * 4 + 1] = v.y;
        t[r * 33 + fq * 4 + 2] = v.z; t[r * 33 + fq * 4 + 3] = v.w;
        __syncthreads();
        float4 o;
        o.x = t[(fq * 4 + 0) * 33 + r]; o.y = t[(fq * 4 + 1) * 33 + r];
        o.z = t[(fq * 4 + 2) * 33 + r]; o.w = t[(fq * 4 + 3) * 33 + r];
        *reinterpret_cast<float4*>(dst + (size_t)(tc * 32 + r) * R + tr * 32 + fq * 4) = o;
    }
}

// ---------------------------------------------------------------------------
// bf16 mma.sync GEMM (m16n8k16), 3xBF16 compensation, double-buffered,
// ldmatrix fragment loading. (R16-proven — unchanged.)
// ---------------------------------------------------------------------------
template<int BM, int BN, int KTOT, int WM, int WN, bool RELU>
__global__ __launch_bounds__(256)
void gemm_bf16(const float* __restrict__ A, const float* __restrict__ Bt,
               float* __restrict__ C, int ldc)
{
    constexpr int LW     = 20;
    constexpr int NWN    = BN / WN;
    constexpr int MSUB   = WM / 16;
    constexpr int NSUB   = WN / 8;
    constexpr int NCHUNK = KTOT / 32;
    constexpr int A_W    = BM * LW;
    constexpr int B_W    = BN * LW;
    constexpr int STAGE_W = 2 * A_W + 2 * B_W;
    constexpr int APT    = BM * 8 / 256;
    constexpr int BPT    = BN * 8 / 256;

    extern __shared__ uint32_t smw[];

    const int tid   = threadIdx.x;
    const int wid   = tid >> 5;
    const int lane  = tid & 31;
    const int brow  = blockIdx.x * BM;
    const int bcol  = blockIdx.y * BN;
    const int warpM = (wid / NWN) * WM;
    const int warpN = (wid % NWN) * WN;
    const int grp   = lane >> 2;
    const int qk    = lane & 3;

    const int laneArow = warpM + (lane & 7) + (lane & 8);
    const int laneAcol = (lane >> 4) << 2;
    const int laneBrow = warpN + (lane & 7);
    const int laneBcol = ((lane >> 3) & 1) << 2;

    float acc[MSUB][NSUB][4] = {};
    float4 pa[APT], pb[BPT];

#pragma unroll
    for (int j = 0; j < APT; ++j) {
        int i = tid + j * 256;
        pa[j] = *reinterpret_cast<const float4*>(
            A + (size_t)(brow + (i >> 3)) * KTOT + ((i & 7) << 2));
    }
#pragma unroll
    for (int j = 0; j < BPT; ++j) {
        int i = tid + j * 256;
        pb[j] = *reinterpret_cast<const float4*>(
            Bt + (size_t)(bcol + (i >> 3)) * KTOT + ((i & 7) << 2));
    }

    for (int c = 0; c < NCHUNK; ++c) {
        uint32_t* Ah = smw + (c & 1) * STAGE_W;
        uint32_t* Al = Ah + A_W;
        uint32_t* Bh = Al + A_W;
        uint32_t* Bl = Bh + B_W;

#pragma unroll
        for (int j = 0; j < APT; ++j) {
            int i = tid + j * 256;
            int r = i >> 3, f = i & 7;
            float4 v = pa[j];
            uint32_t h0 = bf2(v.y, v.x), h1 = bf2(v.w, v.z);
            float hx = __uint_as_float(h0 << 16), hy = __uint_as_float(h0 & 0xffff0000u);
            float hz = __uint_as_float(h1 << 16), hw = __uint_as_float(h1 & 0xffff0000u);
            uint32_t l0 = bf2(v.y - hy, v.x - hx), l1 = bf2(v.w - hw, v.z - hz);
            *reinterpret_cast<uint2*>(&Ah[r * LW + f * 2]) = make_uint2(h0, h1);
            *reinterpret_cast<uint2*>(&Al[r * LW + f * 2]) = make_uint2(l0, l1);
        }
#pragma unroll
        for (int j = 0; j < BPT; ++j) {
            int i = tid + j * 256;
            int r = i >> 3, f = i & 7;
            float4 v = pb[j];
            uint32_t h0 = bf2(v.y, v.x), h1 = bf2(v.w, v.z);
            float hx = __uint_as_float(h0 << 16), hy = __uint_as_float(h0 & 0xffff0000u);
            float hz = __uint_as_float(h1 << 16), hw = __uint_as_float(h1 & 0xffff0000u);
            uint32_t l0 = bf2(v.y - hy, v.x - hx), l1 = bf2(v.w - hw, v.z - hz);
            *reinterpret_cast<uint2*>(&Bh[r * LW + f * 2]) = make_uint2(h0, h1);
            *reinterpret_cast<uint2*>(&Bl[r * LW + f * 2]) = make_uint2(l0, l1);
        }
        if (c + 1 < NCHUNK) {
#pragma unroll
            for (int j = 0; j < APT; ++j) {
                int i = tid + j * 256;
                pa[j] = *reinterpret_cast<const float4*>(
                    A + (size_t)(brow + (i >> 3)) * KTOT + (c + 1) * 32 + ((i & 7) << 2));
            }
#pragma unroll
            for (int j = 0; j < BPT; ++j) {
                int i = tid + j * 256;
                pb[j] = *reinterpret_cast<const float4*>(
                    Bt + (size_t)(bcol + (i >> 3)) * KTOT + (c + 1) * 32 + ((i & 7) << 2));
            }
        }
        __syncthreads();

        const uint32_t aSh = (uint32_t)__cvta_generic_to_shared(Ah)
                           + (uint32_t)((laneArow * LW + laneAcol) * 4);
        const uint32_t bSh = (uint32_t)__cvta_generic_to_shared(Bh)
                           + (uint32_t)((laneBrow * LW + laneBcol) * 4);

#pragma unroll
        for (int ks = 0; ks < 2; ++ks) {
            const int kw = ks * 8;
            uint32_t aH[MSUB][4], aL[MSUB][4];
#pragma unroll
            for (int ms = 0; ms < MSUB; ++ms) {
                uint32_t ad = aSh + (uint32_t)((ms * 16 * LW + kw) * 4);
                ldsm_x4(aH[ms], ad);
                ldsm_x4(aL[ms], ad + A_W * 4);
            }
            uint32_t bH[NSUB][2], bL[NSUB][2];
#pragma unroll
            for (int ns = 0; ns < NSUB; ++ns) {
                uint32_t bd = bSh + (uint32_t)((ns * 8 * LW + kw) * 4);
                ldsm_x2(bH[ns], bd);
                ldsm_x2(bL[ns], bd + B_W * 4);
            }
#pragma unroll
            for (int ms = 0; ms < MSUB; ++ms)
#pragma unroll
                for (int ns = 0; ns < NSUB; ++ns) {
                    mma_bf16(acc[ms][ns], aH[ms], bH[ns]);
                    mma_bf16(acc[ms][ns], aH[ms], bL[ns]);
                    mma_bf16(acc[ms][ns], aL[ms], bH[ns]);
                }
        }
        __syncthreads();
    }

#pragma unroll
    for (int ms = 0; ms < MSUB; ++ms)
#pragma unroll
        for (int ns = 0; ns < NSUB; ++ns) {
            int row = brow + warpM + ms * 16 + grp;
            int col = bcol + warpN + ns * 8 + 2 * qk;
            float2 v0 = make_float2(acc[ms][ns][0], acc[ms][ns][1]);
            float2 v1 = make_float2(acc[ms][ns][2], acc[ms][ns][3]);
            if (RELU) {
                v0.x = fmaxf(v0.x, 0.f); v0.y = fmaxf(v0.y, 0.f);
                v1.x = fmaxf(v1.x, 0.f); v1.y = fmaxf(v1.y, 0.f);
            }
            *reinterpret_cast<float2*>(C + (size_t)row * ldc + col)       = v0;
            *reinterpret_cast<float2*>(C + (size_t)(row + 8) * ldc + col) = v1;
        }
}

// ---------------------------------------------------------------------------
// K4: agg2 + log_softmax. One warp per node. Three-phase: all indices, then
// all 8 loads batched (MLP=8), then ordered fma reduce (bitwise-identical).
// ---------------------------------------------------------------------------
__global__ __launch_bounds__(256)
void agg_lsm_kernel(const float* __restrict__ T, const int* __restrict__ edge,
                    const unsigned* __restrict__ keep_in, float* __restrict__ out)
{
    const int node = (blockIdx.x * blockDim.x + threadIdx.x) >> 5;
    const int lane = threadIdx.x & 31;
    const int nbh  = lane >> 4;
    const int cq   = lane & 15;
    const int base = (node >> 8) << 8;

    int e = edge[node * DEG + cq];
    unsigned mask = keep_in[node];

    // phase 1: all indices + mask factors
    int   jj[8];
    float fm[8];
#pragma unroll
    for (int t = 0; t < 8; ++t) {
        int nb = 2 * t + nbh;
        int j  = __shfl_sync(0xffffffffu, e, nb);
        unsigned bit = (mask >> nb) & 1u;
        jj[t] = bit ? j : 0;
        fm[t] = (float)bit;
    }
    // phase 2: 8 independent loads issued back-to-back
    float4 v[8];
#pragma unroll
    for (int t = 0; t < 8; ++t)
        v[t] = *reinterpret_cast<const float4*>(
            T + (size_t)(base + jj[t]) * NCLASS + (cq << 2));
    // phase 3: ordered reduce (same order as before -> identical bits)
    float4 a = make_float4(0.f, 0.f, 0.f, 0.f);
#pragma unroll
    for (int t = 0; t < 8; ++t) {
        a.x = fmaf(v[t].x, fm[t], a.x);
        a.y = fmaf(v[t].y, fm[t], a.y);
        a.z = fmaf(v[t].z, fm[t], a.z);
        a.w = fmaf(v[t].w, fm[t], a.w);
    }
    a.x += __shfl_xor_sync(0xffffffffu, a.x, 16);
    a.y += __shfl_xor_sync(0xffffffffu, a.y, 16);
    a.z += __shfl_xor_sync(0xffffffffu, a.z, 16);
    a.w += __shfl_xor_sync(0xffffffffu, a.w, 16);

    float mx = fmaxf(fmaxf(a.x, a.y), fmaxf(a.z, a.w));
#pragma unroll
    for (int o = 8; o; o >>= 1)
        mx = fmaxf(mx, __shfl_xor_sync(0xffffffffu, mx, o));
    float s = expf(a.x - mx) + expf(a.y - mx) + expf(a.z - mx) + expf(a.w - mx);
#pragma unroll
    for (int o = 8; o; o >>= 1)
        s += __shfl_xor_sync(0xffffffffu, s, o);
    float lse = logf(s) + mx;

    if (lane < 16)
        *reinterpret_cast<float4*>(out + (size_t)node * NCLASS + (cq << 2)) =
            make_float4(a.x - lse, a.y - lse, a.z - lse, a.w - lse);
}

// ---------------------------------------------------------------------------
extern "C" void kernel_launch(void* const* d_in, const int* in_sizes, int n_in,
                              void* d_out, int out_size)
{
    const float* x    = (const float*)d_in[0];
    const int*   edge = (const int*)  d_in[1];
    const float* W1   = (const float*)d_in[2];
    const float* W2   = (const float*)d_in[3];
    float* out = (float*)d_out;

    float *gX, *gH, *gT, *gW1t, *gW2t;
    unsigned *gK;
    cudaGetSymbolAddress((void**)&gX,   g_X);
    cudaGetSymbolAddress((void**)&gH,   g_H);
    cudaGetSymbolAddress((void**)&gT,   g_T);
    cudaGetSymbolAddress((void**)&gK,   g_keep);
    cudaGetSymbolAddress((void**)&gW1t, g_W1t);
    cudaGetSymbolAddress((void**)&gW2t, g_W2t);

    constexpr int SMEM1 = 2 * (2 * 128 + 2 * 128) * 20 * 4;   // 81920
    constexpr int SMEM2 = 2 * (2 * 64 + 2 * 64) * 20 * 4;     // 40960
    cudaFuncSetAttribute(agg1_kernel,
                         cudaFuncAttributeMaxDynamicSharedMemorySize, A1_SMEM_B);
    cudaFuncSetAttribute(gemm_bf16<128, 128, 128, 64, 32, true>,
                         cudaFuncAttributeMaxDynamicSharedMemorySize, SMEM1);
    cudaFuncSetAttribute(gemm_bf16<64, 64, 256, 32, 16, false>,
                         cudaFuncAttributeMaxDynamicSharedMemorySize, SMEM2);

    // K1: gX = adj @ x (smem-staged, batched gather) + keep masks + W transposes
    agg1_kernel<<<176, 256, A1_SMEM_B>>>(x, edge, W1, W2, gX, gK, gW1t, gW2t);
    // K2: gH = relu(gX @ W1)
    gemm_bf16<128, 128, 128, 64, 32, true>
        <<<dim3(64, 2), 256, SMEM1>>>(gX, gW1t, gH, NHID);
    // K3: gT = gH @ W2
    gemm_bf16<64, 64, 256, 32, 16, false>
        <<<dim3(128, 1), 256, SMEM2>>>(gH, gW2t, gT, NCLASS);
    // K4: out = log_softmax(adj @ gT)  (batched gather)
    agg_lsm_kernel<<<NN / 8, 256>>>(gT, edge, gK, out);
}